// round 9
// baseline (speedup 1.0000x reference)
#include <cuda_runtime.h>
#include <math.h>

#define NB    256
#define TP    32
#define TFUT  256
#define HH    100
#define NF    275
#define HGG   75
#define HOO   75
#define NTHR  288
#define NCTA  128

// ---- transposed/packed weights in global scratch ----
// g_W13P: [0,28050) W1P[(kp*275+n)*2+r] (k=2kp+r, 51 kp, pad k=101..); [28050,28052) pad;
//         [28052,55652) W3P[((half*69+kp)*100+n)*2+r] (k=half*138+2kp+r, k=275 -> 0)
__device__ __align__(16) float g_W13P[55652];
__device__ __align__(16) float g_W2T[276 * 276];   // W2T[k*276+n]; col 275 = 0, row 275 = 0
__device__ __align__(16) float g_WhhT[100 * 300];
__device__ __align__(16) float g_oW1T[100 * 75];
__device__ __align__(16) float g_oW2T[75 * 75];
__device__ float g_hB[NB * HH];
__device__ float g_gx[NB * 2];
__device__ float g_z0[NB * HH];

// ---- shared layout (float offsets), total 57912 floats = 231,648 B ----
#define OFF_W1P  0
#define OFF_W3P  28052
#define OFF_IN   55652   // float2[102] (slot 101 = zero pad)
#define OFF_HID  55856   // float2[276] (slot 275 = zero pad)
#define OFF_A2   56408   // float2[276]
#define OFF_Y    56960   // float2[100]
#define OFF_KS   57160   // float2[100]
#define OFF_PART 57360   // float4[138]
#define SMEM_BYTES (57912 * 4)

__device__ __forceinline__ float leaky1(float x) {
    const float SL = 1.0f / 5.5f;
    return x >= 0.f ? x : x * SL;
}
__device__ __forceinline__ float sigm1(float x) { return 1.f / (1.f + expf(-x)); }

// ---- W2 ring-pipeline macros (16-row chunks, float2 = 2 outputs per thread) ----
#define W2_REFILL(R, ROW0)                                                    \
    _Pragma("unroll")                                                         \
    for (int i_ = 0; i_ < 16; i_++)                                           \
        R[i_] = __ldcg((const float2*)(p + ((ROW0) + i_) * 276));

#define W2_CONSUME(R, C) {                                                    \
    const float4* xx_ = (const float4*)(x2 + (C) * 16);                       \
    _Pragma("unroll")                                                         \
    for (int ii_ = 0; ii_ < 8; ii_++) {                                       \
        float4 xv_ = xx_[ii_];                                                \
        ac.x = fmaf(R[2*ii_].x,   xv_.x, ac.x);                               \
        ac.y = fmaf(R[2*ii_].x,   xv_.y, ac.y);                               \
        ac.z = fmaf(R[2*ii_].y,   xv_.x, ac.z);                               \
        ac.w = fmaf(R[2*ii_].y,   xv_.y, ac.w);                               \
        bc.x = fmaf(R[2*ii_+1].x, xv_.z, bc.x);                               \
        bc.y = fmaf(R[2*ii_+1].x, xv_.w, bc.y);                               \
        bc.z = fmaf(R[2*ii_+1].y, xv_.z, bc.z);                               \
        bc.w = fmaf(R[2*ii_+1].y, xv_.w, bc.w);                               \
    } }

// ---- Layer-3 partial: output n, one k-half (69 pairs), W3P in SMEM ----
__device__ __forceinline__ float2 dotW3(const float2* __restrict__ wp,
                                        const float2* __restrict__ x2base) {
    const float4* x4 = (const float4*)x2base;
    float a0 = 0.f, a1 = 0.f, b0 = 0.f, b1 = 0.f;
#pragma unroll
    for (int c = 0; c < 17; c++) {
        float2 wr[4]; float4 xr[4];
#pragma unroll
        for (int i = 0; i < 4; i++) { wr[i] = wp[(c * 4 + i) * 100]; xr[i] = x4[c * 4 + i]; }
#pragma unroll
        for (int i = 0; i < 4; i++) {
            a0 = fmaf(wr[i].x, xr[i].x, a0); a1 = fmaf(wr[i].x, xr[i].y, a1);
            b0 = fmaf(wr[i].y, xr[i].z, b0); b1 = fmaf(wr[i].y, xr[i].w, b1);
        }
    }
    {   // kp = 68
        float2 w = wp[68 * 100]; float4 x = x4[68];
        a0 = fmaf(w.x, x.x, a0); a1 = fmaf(w.x, x.y, a1);
        b0 = fmaf(w.y, x.z, b0); b1 = fmaf(w.y, x.w, b1);
    }
    return make_float2(a0 + b0, a1 + b1);
}

// ---- One RK4 stage: W2 prefetch -> L1 -> L2(pipelined) -> L3 -> fused update ----
__device__ __forceinline__ void field_stage(int tid, float* sm, int stage,
        float2 dt, float2 tnext, bool write_in,
        float rb1, float rb2a, float rb2b, float rb3) {
    float2* s_in  = (float2*)(sm + OFF_IN);
    float2* s_hid = (float2*)(sm + OFF_HID);
    float2* s_a2  = (float2*)(sm + OFF_A2);
    float2* s_y   = (float2*)(sm + OFF_Y);
    float2* s_ks  = (float2*)(sm + OFF_KS);
    float4* s_p4  = (float4*)(sm + OFF_PART);
    float2* s_p2  = (float2*)(sm + OFF_PART);

    int g = tid / 144, j = tid - g * 144;
    bool act = (j < 138);
    int n0 = 2 * j;
    const float* p = g_W2T + (g * 138) * 276 + n0;

    // ---- W2 prefetch: rows 0..47 + tail 128..137 issued BEFORE L1 compute ----
    float2 r0[16], r1[16], r2[16], tl[10];
    if (act) {
        W2_REFILL(r0, 0)
        W2_REFILL(r1, 16)
        W2_REFILL(r2, 32)
#pragma unroll
        for (int i = 0; i < 10; i++)
            tl[i] = __ldcg((const float2*)(p + (128 + i) * 276));
    }

    // ---- L1: 101 -> 275 (W1P paired in smem) ----
    if (tid < NF) {
        const float2* wp = ((const float2*)(sm + OFF_W1P)) + tid;
        const float4* x4 = (const float4*)(sm + OFF_IN);
        float a0 = rb1, a1 = rb1, b0 = 0.f, b1 = 0.f;
#pragma unroll
        for (int c = 0; c < 12; c++) {
            float2 wr[4]; float4 xr[4];
#pragma unroll
            for (int i = 0; i < 4; i++) { wr[i] = wp[(c * 4 + i) * 275]; xr[i] = x4[c * 4 + i]; }
#pragma unroll
            for (int i = 0; i < 4; i++) {
                a0 = fmaf(wr[i].x, xr[i].x, a0); a1 = fmaf(wr[i].x, xr[i].y, a1);
                b0 = fmaf(wr[i].y, xr[i].z, b0); b1 = fmaf(wr[i].y, xr[i].w, b1);
            }
        }
#pragma unroll
        for (int kp = 48; kp < 51; kp++) {
            float2 w = wp[kp * 275]; float4 x = x4[kp];
            a0 = fmaf(w.x, x.x, a0); a1 = fmaf(w.x, x.y, a1);
            b0 = fmaf(w.y, x.z, b0); b1 = fmaf(w.y, x.w, b1);
        }
        s_hid[tid] = make_float2(tanhf(a0 + b0), tanhf(a1 + b1));
    }
    __syncthreads();

    // ---- L2: 275 -> 275, ring-buffered stream, k-split over 2 groups ----
    float4 acc;
    if (act) {
        const float2* x2 = ((const float2*)(sm + OFF_HID)) + g * 138;
        float4 ac = make_float4(0.f, 0.f, 0.f, 0.f);
        float4 bc = make_float4(0.f, 0.f, 0.f, 0.f);
        W2_CONSUME(r0, 0) W2_REFILL(r0, 48)
        W2_CONSUME(r1, 1) W2_REFILL(r1, 64)
        W2_CONSUME(r2, 2) W2_REFILL(r2, 80)
        W2_CONSUME(r0, 3) W2_REFILL(r0, 96)
        W2_CONSUME(r1, 4) W2_REFILL(r1, 112)
        W2_CONSUME(r2, 5)
        W2_CONSUME(r0, 6)
        W2_CONSUME(r1, 7)
#pragma unroll
        for (int i = 0; i < 10; i++) {
            float2 xv = x2[128 + i];
            if (i & 1) {
                bc.x = fmaf(tl[i].x, xv.x, bc.x); bc.y = fmaf(tl[i].x, xv.y, bc.y);
                bc.z = fmaf(tl[i].y, xv.x, bc.z); bc.w = fmaf(tl[i].y, xv.y, bc.w);
            } else {
                ac.x = fmaf(tl[i].x, xv.x, ac.x); ac.y = fmaf(tl[i].x, xv.y, ac.y);
                ac.z = fmaf(tl[i].y, xv.x, ac.z); ac.w = fmaf(tl[i].y, xv.y, ac.w);
            }
        }
        acc = make_float4(ac.x + bc.x, ac.y + bc.y, ac.z + bc.z, ac.w + bc.w);
        if (g) s_p4[j] = acc;
    }
    __syncthreads();
    if (act && !g) {
        float4 pp = s_p4[j];
        s_a2[n0]     = make_float2(tanhf(acc.x + pp.x + rb2a), tanhf(acc.y + pp.y + rb2a));
        s_a2[n0 + 1] = make_float2(tanhf(acc.z + pp.z + rb2b), tanhf(acc.w + pp.w + rb2b));
    }
    __syncthreads();

    // ---- L3: 275 -> 100 (W3P paired in smem, k-split), fused RK4 update ----
    float2 a3 = make_float2(0.f, 0.f);
    if (tid < 100) {
        a3 = dotW3(((const float2*)(sm + OFF_W3P)) + tid, (const float2*)(sm + OFF_A2));
    } else if (tid < 200) {
        s_p2[tid - 100] = dotW3(((const float2*)(sm + OFF_W3P)) + 69 * 100 + (tid - 100),
                                ((const float2*)(sm + OFF_A2)) + 138);
    }
    __syncthreads();
    if (tid < 100) {
        float2 pp = s_p2[tid];
        float2 f = make_float2(tanhf(a3.x + pp.x + rb3), tanhf(a3.y + pp.y + rb3));
        float2 y = s_y[tid];
        if (stage == 0) {
            s_ks[tid] = f;
            s_in[1 + tid] = make_float2(fmaf(0.5f * dt.x, f.x, y.x),
                                        fmaf(0.5f * dt.y, f.y, y.y));
        } else if (stage == 1) {
            float2 k = s_ks[tid];
            s_ks[tid] = make_float2(k.x + 2.f * f.x, k.y + 2.f * f.y);
            s_in[1 + tid] = make_float2(fmaf(0.5f * dt.x, f.x, y.x),
                                        fmaf(0.5f * dt.y, f.y, y.y));
        } else if (stage == 2) {
            float2 k = s_ks[tid];
            s_ks[tid] = make_float2(k.x + 2.f * f.x, k.y + 2.f * f.y);
            s_in[1 + tid] = make_float2(fmaf(dt.x, f.x, y.x),
                                        fmaf(dt.y, f.y, y.y));
        } else {
            float2 k = s_ks[tid];
            float2 yn = make_float2(y.x + dt.x * (k.x + f.x) / 6.f,
                                    y.y + dt.y * (k.y + f.y) / 6.f);
            s_y[tid] = yn;
            if (write_in) s_in[1 + tid] = yn;
        }
        if (tid == 0 && (stage < 3 || write_in)) s_in[0] = tnext;
    }
    __syncthreads();
}

// ---- RK4, NSUB=2 ----
__device__ __forceinline__ void integrate2(int tid, float* sm, float2 t0, float2 t1,
        float rb1, float rb2a, float rb2b, float rb3) {
    float2* s_in = (float2*)(sm + OFF_IN);
    float2* s_y  = (float2*)(sm + OFF_Y);
    float2 dt = make_float2((t1.x - t0.x) * 0.5f, (t1.y - t0.y) * 0.5f);
    if (tid < HH) s_in[1 + tid] = s_y[tid];
    if (tid == 0) s_in[0] = t0;
    __syncthreads();
#pragma unroll 1
    for (int st = 0; st < 8; st++) {
        int stage = st & 3, sub = st >> 2;
        float2 tb = make_float2(t0.x + sub * dt.x, t0.y + sub * dt.y);
        float2 tnext = (stage <= 1)
            ? make_float2(tb.x + 0.5f * dt.x, tb.y + 0.5f * dt.y)
            : make_float2(tb.x + dt.x, tb.y + dt.y);
        field_stage(tid, sm, stage, dt, tnext, (st == 3), rb1, rb2a, rb2b, rb3);
    }
}

// ---- prep: build packed/transposed weight copies ----
__global__ void prep_kernel(const float* __restrict__ fW1, const float* __restrict__ fW2,
                            const float* __restrict__ fW3, const float* __restrict__ Whh,
                            const float* __restrict__ oW1, const float* __restrict__ oW2) {
    for (int i = blockIdx.x * blockDim.x + threadIdx.x; i < 174953;
         i += gridDim.x * blockDim.x) {
        if (i < 55652) {
            if (i < 28050) {
                int q = i >> 1, r = i & 1;
                int kp = q / 275, n = q % 275;
                int k = 2 * kp + r;
                g_W13P[i] = (k < 101) ? fW1[n * 101 + k] : 0.f;
            } else if (i < 28052) {
                g_W13P[i] = 0.f;
            } else {
                int jj = i - 28052;
                int q = jj >> 1, r = jj & 1;
                int hk = q / 100, n = q % 100;
                int half = hk / 69, kp = hk % 69;
                int k = half * 138 + 2 * kp + r;
                g_W13P[i] = (k < 275) ? fW3[n * 275 + k] : 0.f;
            }
        } else if (i < 131828) {
            int jj = i - 55652, k = jj / 276, n = jj % 276;
            g_W2T[jj] = (n < 275 && k < 275) ? fW2[n * 275 + k] : 0.f;
        } else if (i < 161828) {
            int jj = i - 131828, k = jj / 300, n = jj % 300;
            g_WhhT[jj] = Whh[n * 100 + k];
        } else if (i < 169328) {
            int jj = i - 161828, k = jj / 75, n = jj % 75;
            g_oW1T[jj] = oW1[n * 100 + k];
        } else {
            int jj = i - 169328, k = jj / 75, n = jj % 75;
            g_oW2T[jj] = oW2[n * 75 + k];
        }
    }
}

// ---- encode ----
__global__ void __launch_bounds__(NTHR, 1) encode_kernel(
        const float* __restrict__ past, const float* __restrict__ h0,
        const float* __restrict__ fb1, const float* __restrict__ fb2,
        const float* __restrict__ fb3,
        const float* __restrict__ Wih, const float* __restrict__ bih,
        const float* __restrict__ bhh) {
    extern __shared__ float sm[];
    int tid = threadIdx.x;
    int r0 = blockIdx.x * 2, r1 = r0 + 1;

    const float4* src = (const float4*)g_W13P;
    float4* dst = (float4*)sm;
    for (int i = tid; i < 55652 / 4; i += NTHR) dst[i] = src[i];

    float rb1 = (tid < NF) ? __ldg(fb1 + tid) : 0.f;
    int g = tid / 144, j = tid - g * 144;
    float rb2a = 0.f, rb2b = 0.f;
    if (g == 0 && j < 138) {
        rb2a = __ldg(fb2 + 2 * j);
        rb2b = (2 * j + 1 < NF) ? __ldg(fb2 + 2 * j + 1) : 0.f;
    }
    float rb3 = (tid < HH) ? __ldg(fb3 + tid) : 0.f;

    float2* s_y   = (float2*)(sm + OFF_Y);
    float2* s_u   = (float2*)(sm + OFF_HID);   // [200] aliased
    float2* s_inn = (float2*)(sm + OFF_A2);    // [100]
    float2* s_hn  = (float2*)(sm + OFF_PART);  // [100]
    if (tid < HH) s_y[tid] = make_float2(h0[r0 * HH + tid], h0[r1 * HH + tid]);
    if (tid == 0) {
        ((float2*)(sm + OFF_HID))[275] = make_float2(0.f, 0.f);
        ((float2*)(sm + OFF_IN))[101] = make_float2(0.f, 0.f);
    }
    __syncthreads();

    float2 tprev = make_float2(0.f, 0.f);
    for (int step = 0; step < TP; step++) {
        float2 tcur = make_float2(past[(r0 * TP + step) * 2], past[(r1 * TP + step) * 2]);
        float2 t0 = (step == 0) ? make_float2(tcur.x - 1.f, tcur.y - 1.f) : tprev;
        integrate2(tid, sm, t0, tcur, rb1, rb2a, rb2b, rb3);

        float2 x = make_float2(past[(r0 * TP + step) * 2 + 1],
                               past[(r1 * TP + step) * 2 + 1]);
        const float4* y4 = (const float4*)(sm + OFF_Y);
        for (int jj = tid; jj < 300; jj += NTHR) {
            float bh = __ldg(bhh + jj);
            float a0 = bh, a1 = bh, b0 = 0.f, b1 = 0.f;
#pragma unroll 10
            for (int k = 0; k < 100; k += 2) {
                float w0 = __ldcg(g_WhhT + k * 300 + jj);
                float w1 = __ldcg(g_WhhT + (k + 1) * 300 + jj);
                float4 y = y4[k >> 1];
                a0 = fmaf(w0, y.x, a0); a1 = fmaf(w0, y.y, a1);
                b0 = fmaf(w1, y.z, b0); b1 = fmaf(w1, y.w, b1);
            }
            a0 += b0; a1 += b1;
            float wi = __ldg(Wih + jj), bi = __ldg(bih + jj);
            float2 gi = make_float2(fmaf(wi, x.x, bi), fmaf(wi, x.y, bi));
            if (jj < 200) s_u[jj] = make_float2(gi.x + a0, gi.y + a1);
            else { s_inn[jj - 200] = gi; s_hn[jj - 200] = make_float2(a0, a1); }
        }
        __syncthreads();
        if (tid < HH) {
            float2 u1 = s_u[tid], u2 = s_u[HH + tid];
            float2 gin = s_inn[tid], ghn = s_hn[tid], h = s_y[tid];
            float rx = sigm1(u1.x), ry = sigm1(u1.y);
            float zx = sigm1(u2.x), zy = sigm1(u2.y);
            float nx = tanhf(gin.x + rx * ghn.x), ny = tanhf(gin.y + ry * ghn.y);
            s_y[tid] = make_float2((1.f - zx) * nx + zx * h.x,
                                   (1.f - zy) * ny + zy * h.y);
        }
        __syncthreads();
        tprev = tcur;
    }
    if (tid < HH) {
        g_hB[r0 * HH + tid] = s_y[tid].x;
        g_hB[r1 * HH + tid] = s_y[tid].y;
    }
}

// ---- decoder head ----
__global__ void gx_kernel(const float* __restrict__ gW1, const float* __restrict__ gb1,
                          const float* __restrict__ gW2, const float* __restrict__ gb2,
                          const float* __restrict__ gW3, const float* __restrict__ gb3) {
    int b = blockIdx.x, tid = threadIdx.x;
    __shared__ float sh[HH], s1[HGG], s2[HGG];
    for (int k = tid; k < HH; k += blockDim.x) sh[k] = g_hB[b * HH + k];
    __syncthreads();
    if (tid < HGG) {
        float a = __ldg(gb1 + tid);
        const float* w = gW1 + tid * HH;
        for (int k = 0; k < HH; k++) a = fmaf(__ldg(w + k), sh[k], a);
        s1[tid] = leaky1(a);
    }
    __syncthreads();
    if (tid < HGG) {
        float a = __ldg(gb2 + tid);
        const float* w = gW2 + tid * HGG;
        for (int k = 0; k < HGG; k++) a = fmaf(__ldg(w + k), s1[k], a);
        s2[tid] = leaky1(a);
    }
    __syncthreads();
    if (tid < 2) {
        float a = __ldg(gb3 + tid);
        const float* w = gW3 + tid * HGG;
        for (int k = 0; k < HGG; k++) a = fmaf(__ldg(w + k), s2[k], a);
        g_gx[b * 2 + tid] = a;
    }
}

__global__ void z0_kernel(const float* __restrict__ eps) {
    int b = blockIdx.x, h = threadIdx.x;
    float loc, scale;
    if (b < NB / 2) {
        loc   = g_gx[(2 * b) * 2 + 0];
        scale = g_gx[(2 * b + 1) * 2 + 0];
    } else {
        int i = 2 * (b - NB / 2);
        loc   = fabsf(g_gx[i * 2 + 1]);
        scale = fabsf(g_gx[(i + 1) * 2 + 1]);
    }
    g_z0[b * HH + h] = loc + scale * eps[h * NB + b];
}

// ---- rollout output MLP ----
__device__ __forceinline__ void out_mlp(int tid, int s, int r0, int r1, float* sm,
        float rob1, float rob2,
        const float* __restrict__ oW3, const float* __restrict__ ob3,
        float* __restrict__ out) {
    float2* s_o1 = (float2*)(sm + OFF_HID);
    float2* s_o2 = (float2*)(sm + OFF_A2);
    if (tid < HOO) {
        const float4* y4 = (const float4*)(sm + OFF_Y);
        float a0 = rob1, a1 = rob1, b0 = 0.f, b1 = 0.f;
#pragma unroll 10
        for (int k = 0; k < 100; k += 2) {
            float w0 = __ldcg(g_oW1T + k * 75 + tid);
            float w1 = __ldcg(g_oW1T + (k + 1) * 75 + tid);
            float4 y = y4[k >> 1];
            a0 = fmaf(w0, y.x, a0); a1 = fmaf(w0, y.y, a1);
            b0 = fmaf(w1, y.z, b0); b1 = fmaf(w1, y.w, b1);
        }
        s_o1[tid] = make_float2(leaky1(a0 + b0), leaky1(a1 + b1));
    }
    __syncthreads();
    if (tid < HOO) {
        const float4* h4 = (const float4*)(sm + OFF_HID);
        float a0 = rob2, a1 = rob2, b0 = 0.f, b1 = 0.f;
#pragma unroll 8
        for (int k = 0; k + 1 < HOO; k += 2) {
            float w0 = __ldcg(g_oW2T + k * 75 + tid);
            float w1 = __ldcg(g_oW2T + (k + 1) * 75 + tid);
            float4 h = h4[k >> 1];
            a0 = fmaf(w0, h.x, a0); a1 = fmaf(w0, h.y, a1);
            b0 = fmaf(w1, h.z, b0); b1 = fmaf(w1, h.w, b1);
        }
        {
            float w0 = __ldcg(g_oW2T + 74 * 75 + tid);
            float2 h = s_o1[74];
            a0 = fmaf(w0, h.x, a0); a1 = fmaf(w0, h.y, a1);
        }
        s_o2[tid] = make_float2(leaky1(a0 + b0), leaky1(a1 + b1));
    }
    __syncthreads();
    if (tid < 32) {
        float a0 = 0.f, a1 = 0.f;
        for (int k = tid; k < HOO; k += 32) {
            float wv = __ldg(oW3 + k);
            float2 h = s_o2[k];
            a0 = fmaf(wv, h.x, a0); a1 = fmaf(wv, h.y, a1);
        }
#pragma unroll
        for (int o = 16; o; o >>= 1) {
            a0 += __shfl_down_sync(0xffffffffu, a0, o);
            a1 += __shfl_down_sync(0xffffffffu, a1, o);
        }
        if (tid == 0) {
            float b = __ldg(ob3);
            out[r0 * TFUT + s] = a0 + b;
            out[r1 * TFUT + s] = a1 + b;
        }
    }
    __syncthreads();
}

__global__ void __launch_bounds__(NTHR, 1) rollout_kernel(
        const float* __restrict__ tf_,
        const float* __restrict__ fb1, const float* __restrict__ fb2,
        const float* __restrict__ fb3,
        const float* __restrict__ ob1, const float* __restrict__ ob2,
        const float* __restrict__ oW3, const float* __restrict__ ob3,
        float* __restrict__ out) {
    extern __shared__ float sm[];
    int tid = threadIdx.x;
    int r0 = blockIdx.x * 2, r1 = r0 + 1;

    const float4* src = (const float4*)g_W13P;
    float4* dst = (float4*)sm;
    for (int i = tid; i < 55652 / 4; i += NTHR) dst[i] = src[i];

    float rb1 = (tid < NF) ? __ldg(fb1 + tid) : 0.f;
    int g = tid / 144, j = tid - g * 144;
    float rb2a = 0.f, rb2b = 0.f;
    if (g == 0 && j < 138) {
        rb2a = __ldg(fb2 + 2 * j);
        rb2b = (2 * j + 1 < NF) ? __ldg(fb2 + 2 * j + 1) : 0.f;
    }
    float rb3 = (tid < HH) ? __ldg(fb3 + tid) : 0.f;
    float rob1 = (tid < HOO) ? __ldg(ob1 + tid) : 0.f;
    float rob2 = (tid < HOO) ? __ldg(ob2 + tid) : 0.f;

    float2* s_y = (float2*)(sm + OFF_Y);
    if (tid < HH) s_y[tid] = make_float2(g_z0[r0 * HH + tid], g_z0[r1 * HH + tid]);
    if (tid == 0) {
        ((float2*)(sm + OFF_HID))[275] = make_float2(0.f, 0.f);
        ((float2*)(sm + OFF_IN))[101] = make_float2(0.f, 0.f);
    }
    __syncthreads();

    out_mlp(tid, 0, r0, r1, sm, rob1, rob2, oW3, ob3, out);

    float2 tprev = make_float2(tf_[r0 * TFUT], tf_[r1 * TFUT]);
    for (int s = 1; s < TFUT; s++) {
        float2 tcur = make_float2(tf_[r0 * TFUT + s], tf_[r1 * TFUT + s]);
        integrate2(tid, sm, tprev, tcur, rb1, rb2a, rb2b, rb3);
        out_mlp(tid, s, r0, r1, sm, rob1, rob2, oW3, ob3, out);
        tprev = tcur;
    }
}

extern "C" void kernel_launch(void* const* d_in, const int* in_sizes, int n_in,
                              void* d_out, int out_size) {
    const float* past = (const float*)d_in[0];
    const float* h0   = (const float*)d_in[1];
    const float* t_fu = (const float*)d_in[2];
    const float* eps  = (const float*)d_in[3];
    const float* fW1  = (const float*)d_in[4];
    const float* fb1  = (const float*)d_in[5];
    const float* fW2  = (const float*)d_in[6];
    const float* fb2  = (const float*)d_in[7];
    const float* fW3  = (const float*)d_in[8];
    const float* fb3  = (const float*)d_in[9];
    const float* Wih  = (const float*)d_in[10];
    const float* Whh  = (const float*)d_in[11];
    const float* bih  = (const float*)d_in[12];
    const float* bhh  = (const float*)d_in[13];
    const float* gW1  = (const float*)d_in[14];
    const float* gb1  = (const float*)d_in[15];
    const float* gW2  = (const float*)d_in[16];
    const float* gb2  = (const float*)d_in[17];
    const float* gW3  = (const float*)d_in[18];
    const float* gb3  = (const float*)d_in[19];
    const float* oW1  = (const float*)d_in[20];
    const float* ob1  = (const float*)d_in[21];
    const float* oW2  = (const float*)d_in[22];
    const float* ob2  = (const float*)d_in[23];
    const float* oW3  = (const float*)d_in[24];
    const float* ob3  = (const float*)d_in[25];
    float* out = (float*)d_out;

    static bool attr_done = false;
    if (!attr_done) {
        cudaFuncSetAttribute(encode_kernel,
                             cudaFuncAttributeMaxDynamicSharedMemorySize, SMEM_BYTES);
        cudaFuncSetAttribute(rollout_kernel,
                             cudaFuncAttributeMaxDynamicSharedMemorySize, SMEM_BYTES);
        attr_done = true;
    }

    prep_kernel<<<192, 256>>>(fW1, fW2, fW3, Whh, oW1, oW2);
    encode_kernel<<<NCTA, NTHR, SMEM_BYTES>>>(past, h0, fb1, fb2, fb3, Wih, bih, bhh);
    gx_kernel<<<NB, 96>>>(gW1, gb1, gW2, gb2, gW3, gb3);
    z0_kernel<<<NB, HH>>>(eps);
    rollout_kernel<<<NCTA, NTHR, SMEM_BYTES>>>(t_fu, fb1, fb2, fb3,
                                               ob1, ob2, oW3, ob3, out);
}